// round 9
// baseline (speedup 1.0000x reference)
#include <cuda_runtime.h>
#include <cuda_fp16.h>
#include <cstdint>

// ============================================================================
// Problem constants
// ============================================================================
#define B_DIM 8
#define T_DIM 65536
#define TILE_M 512              // t-rows per block (8 warps x 64 rows)
#define HALO 20                 // staged halo before t0 (>=17, mult of 4)
#define XROWS 552               // staged t rows: t0-20 .. t0+531 (2 halves of 276)
#define HALF_R 276
#define S1_PITCH_W 284          // S1 words per c-row (>=276; 284%32=28 -> xpose OK)
#define WJ_BYTES (64 * 128)     // 8192 per tap (o-major rows of 128B, XOR-swizzled)
#define W_BYTES (9 * WJ_BYTES)  // 73728

// smem layout (bytes)
#define OFF_BIAS 0
#define OFF_W    256
#define OFF_X    (OFF_W + W_BYTES)            // 73984
#define OFF_S1   (OFF_X + XROWS * 128)        // 144640
#define SMEM_TOTAL (OFF_S1 + 64 * S1_PITCH_W * 4)  // 217344

// ============================================================================
// Scratch (device globals — no allocation allowed)
// ============================================================================
__device__ __half g_wh[9 * 64 * 64];   // weights as [j][o][c] fp16

// ============================================================================
// Helpers
// ============================================================================
__device__ __forceinline__ uint32_t smem_to_u32(const void* p) {
    uint32_t a;
    asm("{ .reg .u64 t; cvta.to.shared.u64 t, %1; cvt.u32.u64 %0, t; }" : "=r"(a) : "l"(p));
    return a;
}

__device__ __forceinline__ uint32_t pack_half2(float lo, float hi) {
    __half2 h = __floats2half2_rn(lo, hi);
    return *(const uint32_t*)&h;
}

__device__ __forceinline__ void cp_async16(uint32_t dst, const void* src, int src_bytes) {
    asm volatile("cp.async.cg.shared.global [%0], [%1], 16, %2;"
                 :: "r"(dst), "l"(src), "r"(src_bytes) : "memory");
}
#define CP_COMMIT() asm volatile("cp.async.commit_group;" ::: "memory")
#define CP_WAIT0()  asm volatile("cp.async.wait_group 0;" ::: "memory")

__device__ __forceinline__ void ldsm4(uint32_t& r0, uint32_t& r1, uint32_t& r2, uint32_t& r3,
                                      uint32_t addr) {
    asm volatile("ldmatrix.sync.aligned.m8n8.x4.shared.b16 {%0,%1,%2,%3}, [%4];"
                 : "=r"(r0), "=r"(r1), "=r"(r2), "=r"(r3) : "r"(addr));
}

__device__ __forceinline__ void mma16816(float* c, const uint32_t* a, const uint32_t* b) {
    asm volatile("mma.sync.aligned.m16n8k16.row.col.f32.f16.f16.f32 "
                 "{%0,%1,%2,%3}, {%4,%5,%6,%7}, {%8,%9}, {%0,%1,%2,%3};"
                 : "+f"(c[0]), "+f"(c[1]), "+f"(c[2]), "+f"(c[3])
                 : "r"(a[0]), "r"(a[1]), "r"(a[2]), "r"(a[3]), "r"(b[0]), "r"(b[1]));
}

// ============================================================================
// Prologue: weights fp32 [o][c][9] -> fp16 [j][o][c]
// ============================================================================
__global__ void ta_conv_weights(const float* __restrict__ w) {
    int i = blockIdx.x * 256 + threadIdx.x;
    if (i >= 9 * 64 * 64) return;
    int j = i >> 12;
    int rem = i & 4095;
    int o = rem >> 6;
    int c = rem & 63;
    g_wh[j * 4096 + o * 64 + c] = __float2half_rn(w[(o * 64 + c) * 9 + j]);
}

// ============================================================================
// Main kernel: block = [512 t][64 o]; 8 warps, each a 64x64 warp tile.
//   X staged from native fp32 x[b][c][t] via in-smem transpose:
//     A) float4 LDG (coalesced along t) -> S1[c][r] fp32 (2 halves of 276 r)
//     B) transpose-convert: 8 fp32 down c -> one 16B fp16 chunk of X[t][c]
//   Main loop identical to the proven t-major XOR-swizzle version.
// ============================================================================
__global__ __launch_bounds__(256) void ta_main(const float* __restrict__ x,
                                               const float* __restrict__ bias,
                                               float* __restrict__ out) {
    extern __shared__ char smem[];
    uint32_t sb = smem_to_u32(smem);
    int tid = threadIdx.x;
    int wid = tid >> 5;
    int lane = tid & 31;

    int b = blockIdx.x >> 7;                    // 128 blocks per batch element
    int t0 = (blockIdx.x & 127) * TILE_M;

    if (tid < 64) ((float*)(smem + OFF_BIAS))[tid] = bias[tid];

    // ---- weights -> smem via cp.async, SW128-XOR swizzled ----
    {
        const char* wsrc = (const char*)g_wh;
        for (int i = tid; i < 576 * 8; i += 256) {
            int row = i >> 3, ch = i & 7;
            uint32_t dst = sb + OFF_W + row * 128 + ((ch ^ (row & 7)) * 16);
            cp_async16(dst, wsrc + row * 128 + ch * 16, 16);
        }
        CP_COMMIT();
    }

    // ---- stage x: two halves of 276 rows each ----
    for (int h = 0; h < 2; h++) {
        int rbase = h * HALF_R;

        // Phase A: fp32 x[c][t] -> S1[c][r] (coalesced float4 along t)
        {
            int c = tid >> 2;
            int q0 = tid & 3;
            const float* xrow = x + ((size_t)(b * 64 + c)) * T_DIM;
            #pragma unroll 3
            for (int q = q0; q < 69; q += 4) {
                int r = q * 4;                       // 0..272
                int tg = t0 - HALO + rbase + r;      // multiple of 4
                float4 v;
                if (tg >= 0 && tg <= T_DIM - 4) {
                    v = *(const float4*)(xrow + tg);
                } else {
                    v.x = ((unsigned)tg < (unsigned)T_DIM) ? xrow[tg] : 0.f;
                    v.y = ((unsigned)(tg + 1) < (unsigned)T_DIM) ? xrow[tg + 1] : 0.f;
                    v.z = ((unsigned)(tg + 2) < (unsigned)T_DIM) ? xrow[tg + 2] : 0.f;
                    v.w = ((unsigned)(tg + 3) < (unsigned)T_DIM) ? xrow[tg + 3] : 0.f;
                }
                *(float4*)(smem + OFF_S1 + (c * S1_PITCH_W + r) * 4) = v;
            }
        }
        __syncthreads();

        // Phase B: transpose-convert S1 -> X[t][c] (fp16, XOR-swizzled chunks)
        for (int task = tid; task < HALF_R * 8; task += 256) {
            int r = task % HALF_R;                   // lanes ~consecutive r
            int ch = task / HALF_R;                  // 16B chunk (8 c values)
            float f[8];
            #pragma unroll
            for (int i = 0; i < 8; i++)
                f[i] = *(const float*)(smem + OFF_S1 + ((ch * 8 + i) * S1_PITCH_W + r) * 4);
            uint4 hv;
            hv.x = pack_half2(f[0], f[1]);
            hv.y = pack_half2(f[2], f[3]);
            hv.z = pack_half2(f[4], f[5]);
            hv.w = pack_half2(f[6], f[7]);
            int R = rbase + r;
            *(uint4*)(smem + OFF_X + R * 128 + ((ch ^ (R & 7)) * 16)) = hv;
        }
        __syncthreads();
    }

    // lane-dependent ldmatrix address components
    const int a_lrow = lane & 15;
    const int a_lcol = (lane >> 4) << 3;                 // 0 or 8 (halves)
    const int b_lrow = ((lane & 16) >> 1) + (lane & 7);  // 0..15
    const int b_lcol = lane & 8;                         // 0 or 8 (halves)
    const int b_sw = b_lrow & 7;

    const uint32_t wbase = sb + OFF_W;
    const uint32_t xbase = sb + OFF_X;

    float acc[4][8][4];
    #pragma unroll
    for (int mi = 0; mi < 4; mi++)
        #pragma unroll
        for (int ni = 0; ni < 8; ni++)
            #pragma unroll
            for (int r = 0; r < 4; r++) acc[mi][ni][r] = 0.0f;

    CP_WAIT0();
    __syncthreads();

    const int delta[9] = {-17, -16, -15, -1, 0, 1, 15, 16, 17};

    for (int j = 0; j < 9; j++) {
        const int tb = HALO + wid * 64 + delta[j] + a_lrow;  // this lane's base row
        const int a_sw = tb & 7;
        const uint32_t wj = wbase + j * WJ_BYTES;
        #pragma unroll
        for (int kk = 0; kk < 4; kk++) {
            const int c0 = kk * 16;
            const uint32_t achunk = (uint32_t)((((c0 + a_lcol) >> 3) ^ a_sw) * 16);
            const uint32_t bchunk = (uint32_t)((((c0 + b_lcol) >> 3) ^ b_sw) * 16);
            uint32_t a[4][4], bb[4][4];
            #pragma unroll
            for (int mi = 0; mi < 4; mi++)
                ldsm4(a[mi][0], a[mi][1], a[mi][2], a[mi][3],
                      xbase + (uint32_t)(tb + mi * 16) * 128 + achunk);
            #pragma unroll
            for (int bi = 0; bi < 4; bi++)
                ldsm4(bb[bi][0], bb[bi][1], bb[bi][2], bb[bi][3],
                      wj + (uint32_t)(bi * 16 + b_lrow) * 128 + bchunk);
            #pragma unroll
            for (int mi = 0; mi < 4; mi++)
                #pragma unroll
                for (int bi = 0; bi < 4; bi++) {
                    mma16816(acc[mi][2 * bi], a[mi], bb[bi] + 0);
                    mma16816(acc[mi][2 * bi + 1], a[mi], bb[bi] + 2);
                }
        }
    }

    // ---- epilogue: D fragment (row=t, col=o), add bias, store ----
    {
        const float* sbias = (const float*)(smem + OFF_BIAS);
        int trow = t0 + wid * 64 + (lane >> 2);
        int ocol = 2 * (lane & 3);
        #pragma unroll
        for (int mi = 0; mi < 4; mi++) {
            #pragma unroll
            for (int ni = 0; ni < 8; ni++) {
                int t = trow + mi * 16;
                int o = ocol + ni * 8;
                size_t base = ((size_t)b * 64 + o) * T_DIM + t;
                float bz0 = sbias[o], bz1 = sbias[o + 1];
                out[base] = acc[mi][ni][0] + bz0;
                out[base + T_DIM] = acc[mi][ni][1] + bz1;
                out[base + 8] = acc[mi][ni][2] + bz0;
                out[base + T_DIM + 8] = acc[mi][ni][3] + bz1;
            }
        }
    }
}

// ============================================================================
// Launch
// ============================================================================
extern "C" void kernel_launch(void* const* d_in, const int* in_sizes, int n_in,
                              void* d_out, int out_size) {
    const float* x = (const float*)d_in[0];
    const float* w = (const float*)d_in[1];
    const float* bias = (const float*)d_in[2];
    float* out = (float*)d_out;

    cudaFuncSetAttribute(ta_main, cudaFuncAttributeMaxDynamicSharedMemorySize, SMEM_TOTAL);

    ta_conv_weights<<<(9 * 64 * 64 + 255) / 256, 256>>>(w);
    ta_main<<<(B_DIM * T_DIM) / TILE_M, 256, SMEM_TOTAL>>>(x, bias, out);
}

// round 11
// speedup vs baseline: 1.4430x; 1.4430x over previous
#include <cuda_runtime.h>
#include <cuda_fp16.h>
#include <cstdint>

// ============================================================================
// Problem constants
// ============================================================================
#define B_DIM 8
#define T_DIM 65536
#define TILE_M 512            // t-rows per block (one pass, 8 warps x 64 rows)
#define XROWS 546             // staged rows: t0-17 .. t0+528
#define WJ_BYTES (64 * 128)   // 8192 per tap (o-major rows of 128B, swizzled)
#define W_BYTES (9 * WJ_BYTES)  // 73728

// smem layout (bytes) for ta_main
#define OFF_BIAS 0
#define OFF_W    256
#define OFF_X    (OFF_W + W_BYTES)          // 73984 (128B aligned)
#define SMEM_TOTAL (OFF_X + XROWS * 128)    // 143872

// prep scratch layout: s1[t][c], t-major, pitch 66 words
#define P1 66

// ============================================================================
// Scratch (device globals — no allocation allowed)
// ============================================================================
__device__ __half g_xh[(size_t)B_DIM * T_DIM * 64];  // x as [b][t][c] fp16
__device__ __half g_wh[9 * 64 * 64];                 // w as [j][o][c] fp16

// ============================================================================
// Helpers
// ============================================================================
__device__ __forceinline__ uint32_t smem_to_u32(const void* p) {
    uint32_t a;
    asm("{ .reg .u64 t; cvta.to.shared.u64 t, %1; cvt.u32.u64 %0, t; }" : "=r"(a) : "l"(p));
    return a;
}

__device__ __forceinline__ uint32_t pack_half2(float lo, float hi) {
    __half2 h = __floats2half2_rn(lo, hi);
    return *(const uint32_t*)&h;
}

__device__ __forceinline__ void cp_async16(uint32_t dst, const void* src, int src_bytes) {
    asm volatile("cp.async.cg.shared.global [%0], [%1], 16, %2;"
                 :: "r"(dst), "l"(src), "r"(src_bytes) : "memory");
}
#define CP_COMMIT() asm volatile("cp.async.commit_group;" ::: "memory")
#define CP_WAIT0()  asm volatile("cp.async.wait_group 0;" ::: "memory")

__device__ __forceinline__ void ldsm4(uint32_t& r0, uint32_t& r1, uint32_t& r2, uint32_t& r3,
                                      uint32_t addr) {
    asm volatile("ldmatrix.sync.aligned.m8n8.x4.shared.b16 {%0,%1,%2,%3}, [%4];"
                 : "=r"(r0), "=r"(r1), "=r"(r2), "=r"(r3) : "r"(addr));
}

__device__ __forceinline__ void mma16816(float* c, const uint32_t* a, const uint32_t* b) {
    asm volatile("mma.sync.aligned.m16n8k16.row.col.f32.f16.f16.f32 "
                 "{%0,%1,%2,%3}, {%4,%5,%6,%7}, {%8,%9}, {%0,%1,%2,%3};"
                 : "+f"(c[0]), "+f"(c[1]), "+f"(c[2]), "+f"(c[3])
                 : "r"(a[0]), "r"(a[1]), "r"(a[2]), "r"(a[3]), "r"(b[0]), "r"(b[1]));
}

// ============================================================================
// Prologue 1: weights fp32 [o][c][9] -> fp16 [j][o][c]
// ============================================================================
__global__ void ta_conv_weights(const float* __restrict__ w) {
    int i = blockIdx.x * 256 + threadIdx.x;
    if (i >= 9 * 64 * 64) return;
    int j = i >> 12;
    int rem = i & 4095;
    int o = rem >> 6;
    int c = rem & 63;
    g_wh[j * 4096 + o * 64 + c] = __float2half_rn(w[(o * 64 + c) * 9 + j]);
}

// ============================================================================
// Prologue 2: x fp32 [b][c][t] -> fp16 [b][t][c], smem transpose.
//   Block = 128 t x 64 c.  s1[t][c] t-major, pitch 66 words.
//   Phase A: float4 LDG along t -> 4 scalar STS (banks c+8q+2i: conflict-free).
//   Phase B: lane l LDS.64 at s1[r*66+2l] (16-lane phase covers 32 consecutive
//   words -> conflict-free), pack half2, coalesced 128B STG rows.
// ============================================================================
__global__ __launch_bounds__(256) void ta_prep(const float* __restrict__ x) {
    __shared__ float s1[128 * P1];        // 33.8 KB
    int tid = threadIdx.x;
    int wid = tid >> 5;
    int lane = tid & 31;
    int b = blockIdx.y;
    int t0 = blockIdx.x * 128;

    // Phase A: coalesced float4 reads along t, scalar transposed STS
    {
        int c = tid >> 2;
        int q0 = tid & 3;
        const float* xrow = x + ((size_t)(b * 64 + c)) * T_DIM + t0;
        #pragma unroll
        for (int q = q0; q < 32; q += 4) {
            float4 v = *(const float4*)(xrow + q * 4);
            int t = q * 4;
            s1[(t + 0) * P1 + c] = v.x;
            s1[(t + 1) * P1 + c] = v.y;
            s1[(t + 2) * P1 + c] = v.z;
            s1[(t + 3) * P1 + c] = v.w;
        }
    }
    __syncthreads();

    // Phase B: one warp per t-row, float2 LDS + coalesced STG
    {
        uint32_t* orow = (uint32_t*)g_xh;
        #pragma unroll
        for (int r = wid; r < 128; r += 8) {
            float2 f = *(const float2*)(s1 + r * P1 + 2 * lane);
            orow[((size_t)b * T_DIM + t0 + r) * 32 + lane] = pack_half2(f.x, f.y);
        }
    }
}

// ============================================================================
// Main kernel (proven @114us): block = [512 t][64 o]; 8 warps, 64x64 tiles.
//   Smem: swizzled (SW128 XOR) x tile (546 rows) + weights (576 rows).
// ============================================================================
__global__ __launch_bounds__(256) void ta_main(const float* __restrict__ bias,
                                               float* __restrict__ out) {
    extern __shared__ char smem[];
    uint32_t sb = smem_to_u32(smem);
    int tid = threadIdx.x;
    int wid = tid >> 5;
    int lane = tid & 31;

    int b = blockIdx.x >> 7;                    // 128 blocks per batch element
    int t0 = (blockIdx.x & 127) * TILE_M;

    if (tid < 64) ((float*)(smem + OFF_BIAS))[tid] = bias[tid];

    // ---- stage weights + x tile via cp.async, SW128-XOR swizzled ----
    {
        const char* wsrc = (const char*)g_wh;
        for (int i = tid; i < 576 * 8; i += 256) {
            int row = i >> 3, ch = i & 7;
            uint32_t dst = sb + OFF_W + row * 128 + ((ch ^ (row & 7)) * 16);
            cp_async16(dst, wsrc + row * 128 + ch * 16, 16);
        }
        for (int i = tid; i < XROWS * 8; i += 256) {
            int s = i >> 3, ch = i & 7;
            int t = t0 - 17 + s;
            const char* src = (const char*)(g_xh + ((size_t)b * T_DIM + t) * 64) + ch * 16;
            uint32_t dst = sb + OFF_X + s * 128 + ((ch ^ (s & 7)) * 16);
            cp_async16(dst, src, ((unsigned)t < (unsigned)T_DIM) ? 16 : 0);
        }
        CP_COMMIT();
    }

    // lane-dependent ldmatrix address components
    const int a_lrow = lane & 15;
    const int a_lcol = (lane >> 4) << 3;                 // 0 or 8 (halves)
    const int b_lrow = ((lane & 16) >> 1) + (lane & 7);  // 0..15
    const int b_lcol = lane & 8;                         // 0 or 8 (halves)
    const int b_sw = b_lrow & 7;

    const uint32_t wbase = sb + OFF_W;
    const uint32_t xbase = sb + OFF_X;

    float acc[4][8][4];
    #pragma unroll
    for (int mi = 0; mi < 4; mi++)
        #pragma unroll
        for (int ni = 0; ni < 8; ni++)
            #pragma unroll
            for (int r = 0; r < 4; r++) acc[mi][ni][r] = 0.0f;

    CP_WAIT0();
    __syncthreads();

    const int delta[9] = {-17, -16, -15, -1, 0, 1, 15, 16, 17};

    for (int j = 0; j < 9; j++) {
        const int tb = 17 + wid * 64 + delta[j] + a_lrow;  // this lane's base row
        const int a_sw = tb & 7;
        const uint32_t wj = wbase + j * WJ_BYTES;
        #pragma unroll
        for (int kk = 0; kk < 4; kk++) {
            const int c0 = kk * 16;
            const uint32_t achunk = (uint32_t)((((c0 + a_lcol) >> 3) ^ a_sw) * 16);
            const uint32_t bchunk = (uint32_t)((((c0 + b_lcol) >> 3) ^ b_sw) * 16);
            uint32_t a[4][4], bb[4][4];
            #pragma unroll
            for (int mi = 0; mi < 4; mi++)
                ldsm4(a[mi][0], a[mi][1], a[mi][2], a[mi][3],
                      xbase + (uint32_t)(tb + mi * 16) * 128 + achunk);
            #pragma unroll
            for (int bi = 0; bi < 4; bi++)
                ldsm4(bb[bi][0], bb[bi][1], bb[bi][2], bb[bi][3],
                      wj + (uint32_t)(bi * 16 + b_lrow) * 128 + bchunk);
            #pragma unroll
            for (int mi = 0; mi < 4; mi++)
                #pragma unroll
                for (int bi = 0; bi < 4; bi++) {
                    mma16816(acc[mi][2 * bi], a[mi], bb[bi] + 0);
                    mma16816(acc[mi][2 * bi + 1], a[mi], bb[bi] + 2);
                }
        }
    }

    // ---- epilogue: D fragment (row=t, col=o), add bias, store ----
    {
        const float* sbias = (const float*)(smem + OFF_BIAS);
        int trow = t0 + wid * 64 + (lane >> 2);
        int ocol = 2 * (lane & 3);
        #pragma unroll
        for (int mi = 0; mi < 4; mi++) {
            #pragma unroll
            for (int ni = 0; ni < 8; ni++) {
                int t = trow + mi * 16;
                int o = ocol + ni * 8;
                size_t base = ((size_t)b * 64 + o) * T_DIM + t;
                float bz0 = sbias[o], bz1 = sbias[o + 1];
                out[base] = acc[mi][ni][0] + bz0;
                out[base + T_DIM] = acc[mi][ni][1] + bz1;
                out[base + 8] = acc[mi][ni][2] + bz0;
                out[base + T_DIM + 8] = acc[mi][ni][3] + bz1;
            }
        }
    }
}

// ============================================================================
// Launch
// ============================================================================
extern "C" void kernel_launch(void* const* d_in, const int* in_sizes, int n_in,
                              void* d_out, int out_size) {
    const float* x = (const float*)d_in[0];
    const float* w = (const float*)d_in[1];
    const float* bias = (const float*)d_in[2];
    float* out = (float*)d_out;

    cudaFuncSetAttribute(ta_main, cudaFuncAttributeMaxDynamicSharedMemorySize, SMEM_TOTAL);

    ta_conv_weights<<<(9 * 64 * 64 + 255) / 256, 256>>>(w);
    ta_prep<<<dim3(T_DIM / 128, B_DIM), 256>>>(x);
    ta_main<<<(B_DIM * T_DIM) / TILE_M, 256, SMEM_TOTAL>>>(bias, out);
}

// round 14
// speedup vs baseline: 1.5147x; 1.0497x over previous
#include <cuda_runtime.h>
#include <cuda_fp16.h>
#include <cstdint>

// ============================================================================
// Problem constants
// ============================================================================
#define B_DIM 8
#define T_DIM 65536
#define TILE_M 256            // t-rows per block (8 warps x 32 rows)
#define XROWS 290             // staged rows: t0-17 .. t0+272
#define WJ_BYTES (64 * 128)   // 8192 per tap (o-major rows of 128B, swizzled)
#define W_BYTES (9 * WJ_BYTES)  // 73728

// smem layout (bytes) for ta_main
#define OFF_BIAS 0
#define OFF_W    256
#define OFF_X    (OFF_W + W_BYTES)          // 73984 (128B aligned)
#define SMEM_TOTAL (OFF_X + XROWS * 128)    // 111104  (x2 CTAs = 222208)

// prep scratch layout: s1[t][c], t-major, pitch 66 words
#define P1 66

// ============================================================================
// Scratch (device globals — no allocation allowed)
// ============================================================================
__device__ __half g_xh[(size_t)B_DIM * T_DIM * 64];  // x as [b][t][c] fp16
__device__ __half g_wh[9 * 64 * 64];                 // w as [j][o][c] fp16

// ============================================================================
// Helpers
// ============================================================================
__device__ __forceinline__ uint32_t smem_to_u32(const void* p) {
    uint32_t a;
    asm("{ .reg .u64 t; cvta.to.shared.u64 t, %1; cvt.u32.u64 %0, t; }" : "=r"(a) : "l"(p));
    return a;
}

__device__ __forceinline__ uint32_t pack_half2(float lo, float hi) {
    __half2 h = __floats2half2_rn(lo, hi);
    return *(const uint32_t*)&h;
}

__device__ __forceinline__ void cp_async16(uint32_t dst, const void* src, int src_bytes) {
    asm volatile("cp.async.cg.shared.global [%0], [%1], 16, %2;"
                 :: "r"(dst), "l"(src), "r"(src_bytes) : "memory");
}
#define CP_COMMIT() asm volatile("cp.async.commit_group;" ::: "memory")
#define CP_WAIT0()  asm volatile("cp.async.wait_group 0;" ::: "memory")

__device__ __forceinline__ void ldsm4(uint32_t& r0, uint32_t& r1, uint32_t& r2, uint32_t& r3,
                                      uint32_t addr) {
    asm volatile("ldmatrix.sync.aligned.m8n8.x4.shared.b16 {%0,%1,%2,%3}, [%4];"
                 : "=r"(r0), "=r"(r1), "=r"(r2), "=r"(r3) : "r"(addr));
}

__device__ __forceinline__ void mma16816(float* c, const uint32_t* a, const uint32_t* b) {
    asm volatile("mma.sync.aligned.m16n8k16.row.col.f32.f16.f16.f32 "
                 "{%0,%1,%2,%3}, {%4,%5,%6,%7}, {%8,%9}, {%0,%1,%2,%3};"
                 : "+f"(c[0]), "+f"(c[1]), "+f"(c[2]), "+f"(c[3])
                 : "r"(a[0]), "r"(a[1]), "r"(a[2]), "r"(a[3]), "r"(b[0]), "r"(b[1]));
}

// ============================================================================
// Prologue 1: weights fp32 [o][c][9] -> fp16 [j][o][c]
// ============================================================================
__global__ void ta_conv_weights(const float* __restrict__ w) {
    int i = blockIdx.x * 256 + threadIdx.x;
    if (i >= 9 * 64 * 64) return;
    int j = i >> 12;
    int rem = i & 4095;
    int o = rem >> 6;
    int c = rem & 63;
    g_wh[j * 4096 + o * 64 + c] = __float2half_rn(w[(o * 64 + c) * 9 + j]);
}

// ============================================================================
// Prologue 2: x fp32 [b][c][t] -> fp16 [b][t][c], smem transpose (proven).
// ============================================================================
__global__ __launch_bounds__(256) void ta_prep(const float* __restrict__ x) {
    __shared__ float s1[128 * P1];        // 33.8 KB
    int tid = threadIdx.x;
    int wid = tid >> 5;
    int lane = tid & 31;
    int b = blockIdx.y;
    int t0 = blockIdx.x * 128;

    // Phase A: coalesced float4 reads along t, scalar transposed STS
    {
        int c = tid >> 2;
        int q0 = tid & 3;
        const float* xrow = x + ((size_t)(b * 64 + c)) * T_DIM + t0;
        #pragma unroll
        for (int q = q0; q < 32; q += 4) {
            float4 v = *(const float4*)(xrow + q * 4);
            int t = q * 4;
            s1[(t + 0) * P1 + c] = v.x;
            s1[(t + 1) * P1 + c] = v.y;
            s1[(t + 2) * P1 + c] = v.z;
            s1[(t + 3) * P1 + c] = v.w;
        }
    }
    __syncthreads();

    // Phase B: one warp per t-row, float2 LDS + coalesced STG
    {
        uint32_t* orow = (uint32_t*)g_xh;
        #pragma unroll
        for (int r = wid; r < 128; r += 8) {
            float2 f = *(const float2*)(s1 + r * P1 + 2 * lane);
            orow[((size_t)b * T_DIM + t0 + r) * 32 + lane] = pack_half2(f.x, f.y);
        }
    }
}

// ============================================================================
// Main kernel: block = [256 t][64 o]; 8 warps, each a 32x64 warp tile.
//   2 CTAs/SM (<=128 regs via launch_bounds) for latency hiding.
//   Smem: swizzled (SW128 XOR) x tile (290 rows) + weights (576 rows).
// ============================================================================
__global__ __launch_bounds__(256, 2) void ta_main(const float* __restrict__ bias,
                                                  float* __restrict__ out) {
    extern __shared__ char smem[];
    uint32_t sb = smem_to_u32(smem);
    int tid = threadIdx.x;
    int wid = tid >> 5;
    int lane = tid & 31;

    int b = blockIdx.x >> 8;                    // 256 blocks per batch element
    int t0 = (blockIdx.x & 255) * TILE_M;

    if (tid < 64) ((float*)(smem + OFF_BIAS))[tid] = bias[tid];

    // ---- stage weights + x tile via cp.async, SW128-XOR swizzled ----
    {
        const char* wsrc = (const char*)g_wh;
        for (int i = tid; i < 576 * 8; i += 256) {
            int row = i >> 3, ch = i & 7;
            uint32_t dst = sb + OFF_W + row * 128 + ((ch ^ (row & 7)) * 16);
            cp_async16(dst, wsrc + row * 128 + ch * 16, 16);
        }
        for (int i = tid; i < XROWS * 8; i += 256) {
            int s = i >> 3, ch = i & 7;
            int t = t0 - 17 + s;
            const char* src = (const char*)(g_xh + ((size_t)b * T_DIM + t) * 64) + ch * 16;
            uint32_t dst = sb + OFF_X + s * 128 + ((ch ^ (s & 7)) * 16);
            cp_async16(dst, src, ((unsigned)t < (unsigned)T_DIM) ? 16 : 0);
        }
        CP_COMMIT();
    }

    // lane-dependent ldmatrix address components
    const int a_lrow = lane & 15;
    const int a_lcol = (lane >> 4) << 3;                 // 0 or 8 (halves)
    const int b_lrow = ((lane & 16) >> 1) + (lane & 7);  // 0..15
    const int b_lcol = lane & 8;                         // 0 or 8 (halves)
    const int b_sw = b_lrow & 7;

    const uint32_t wbase = sb + OFF_W;
    const uint32_t xbase = sb + OFF_X;

    float acc[2][8][4];
    #pragma unroll
    for (int mi = 0; mi < 2; mi++)
        #pragma unroll
        for (int ni = 0; ni < 8; ni++)
            #pragma unroll
            for (int r = 0; r < 4; r++) acc[mi][ni][r] = 0.0f;

    CP_WAIT0();
    __syncthreads();

    const int delta[9] = {-17, -16, -15, -1, 0, 1, 15, 16, 17};

    for (int j = 0; j < 9; j++) {
        const int tb = 17 + wid * 32 + delta[j] + a_lrow;  // this lane's base row
        const int a_sw = tb & 7;
        const uint32_t wj = wbase + j * WJ_BYTES;
        #pragma unroll
        for (int kk = 0; kk < 4; kk++) {
            const int c0 = kk * 16;
            const uint32_t achunk = (uint32_t)((((c0 + a_lcol) >> 3) ^ a_sw) * 16);
            const uint32_t bchunk = (uint32_t)((((c0 + b_lcol) >> 3) ^ b_sw) * 16);
            uint32_t a[2][4], bb[4][4];
            #pragma unroll
            for (int mi = 0; mi < 2; mi++)
                ldsm4(a[mi][0], a[mi][1], a[mi][2], a[mi][3],
                      xbase + (uint32_t)(tb + mi * 16) * 128 + achunk);
            #pragma unroll
            for (int bi = 0; bi < 4; bi++)
                ldsm4(bb[bi][0], bb[bi][1], bb[bi][2], bb[bi][3],
                      wj + (uint32_t)(bi * 16 + b_lrow) * 128 + bchunk);
            #pragma unroll
            for (int mi = 0; mi < 2; mi++)
                #pragma unroll
                for (int bi = 0; bi < 4; bi++) {
                    mma16816(acc[mi][2 * bi], a[mi], bb[bi] + 0);
                    mma16816(acc[mi][2 * bi + 1], a[mi], bb[bi] + 2);
                }
        }
    }

    // ---- epilogue: D fragment (row=t, col=o), add bias, store ----
    {
        const float* sbias = (const float*)(smem + OFF_BIAS);
        int trow = t0 + wid * 32 + (lane >> 2);
        int ocol = 2 * (lane & 3);
        #pragma unroll
        for (int mi = 0; mi < 2; mi++) {
            #pragma unroll
            for (int ni = 0; ni < 8; ni++) {
                int t = trow + mi * 16;
                int o = ocol + ni * 8;
                size_t base = ((size_t)b * 64 + o) * T_DIM + t;
                float bz0 = sbias[o], bz1 = sbias[o + 1];
                out[base] = acc[mi][ni][0] + bz0;
                out[base + T_DIM] = acc[mi][ni][1] + bz1;
                out[base + 8] = acc[mi][ni][2] + bz0;
                out[base + T_DIM + 8] = acc[mi][ni][3] + bz1;
            }
        }
    }
}

// ============================================================================
// Launch
// ============================================================================
extern "C" void kernel_launch(void* const* d_in, const int* in_sizes, int n_in,
                              void* d_out, int out_size) {
    const float* x = (const float*)d_in[0];
    const float* w = (const float*)d_in[1];
    const float* bias = (const float*)d_in[2];
    float* out = (float*)d_out;

    cudaFuncSetAttribute(ta_main, cudaFuncAttributeMaxDynamicSharedMemorySize, SMEM_TOTAL);

    ta_conv_weights<<<(9 * 64 * 64 + 255) / 256, 256>>>(w);
    ta_prep<<<dim3(T_DIM / 128, B_DIM), 256>>>(x);
    ta_main<<<(B_DIM * T_DIM) / TILE_M, 256, SMEM_TOTAL>>>(bias, out);
}

// round 15
// speedup vs baseline: 1.6948x; 1.1189x over previous
#include <cuda_runtime.h>
#include <cuda_fp16.h>
#include <cstdint>

// ============================================================================
// Problem constants
// ============================================================================
#define B_DIM 8
#define T_DIM 65536
#define TILE_M 256            // t-rows per block (8 warps x 32 rows)
#define XROWS 290             // staged rows: t0-17 .. t0+272
#define WJ_BYTES (64 * 128)   // 8192 per tap (o-major rows of 128B, swizzled)
#define W_BYTES (9 * WJ_BYTES)  // 73728

// smem layout (bytes) for ta_main
#define OFF_BIAS 0
#define OFF_W    256
#define OFF_X    (OFF_W + W_BYTES)          // 73984 (128B aligned)
#define SMEM_TOTAL (OFF_X + XROWS * 128)    // 111104  (x2 CTAs = 222208)

// prep scratch layout: s1[t][c], t-major, pitch 66 words
#define P1 66

// ============================================================================
// Scratch (device globals — no allocation allowed)
// ============================================================================
__device__ __half g_xh[(size_t)B_DIM * T_DIM * 64];  // x as [b][t][c] fp16
__device__ __half g_wh[9 * 64 * 64];                 // w as [j][o][c] fp16

// ============================================================================
// Helpers
// ============================================================================
__device__ __forceinline__ uint32_t smem_to_u32(const void* p) {
    uint32_t a;
    asm("{ .reg .u64 t; cvta.to.shared.u64 t, %1; cvt.u32.u64 %0, t; }" : "=r"(a) : "l"(p));
    return a;
}

__device__ __forceinline__ uint32_t pack_half2(float lo, float hi) {
    __half2 h = __floats2half2_rn(lo, hi);
    return *(const uint32_t*)&h;
}

__device__ __forceinline__ void cp_async16(uint32_t dst, const void* src, int src_bytes) {
    asm volatile("cp.async.cg.shared.global [%0], [%1], 16, %2;"
                 :: "r"(dst), "l"(src), "r"(src_bytes) : "memory");
}
#define CP_COMMIT() asm volatile("cp.async.commit_group;" ::: "memory")
#define CP_WAIT0()  asm volatile("cp.async.wait_group 0;" ::: "memory")

__device__ __forceinline__ void ldsm4(uint32_t& r0, uint32_t& r1, uint32_t& r2, uint32_t& r3,
                                      uint32_t addr) {
    asm volatile("ldmatrix.sync.aligned.m8n8.x4.shared.b16 {%0,%1,%2,%3}, [%4];"
                 : "=r"(r0), "=r"(r1), "=r"(r2), "=r"(r3) : "r"(addr));
}

__device__ __forceinline__ void mma16816(float* c, const uint32_t* a, const uint32_t* b) {
    asm volatile("mma.sync.aligned.m16n8k16.row.col.f32.f16.f16.f32 "
                 "{%0,%1,%2,%3}, {%4,%5,%6,%7}, {%8,%9}, {%0,%1,%2,%3};"
                 : "+f"(c[0]), "+f"(c[1]), "+f"(c[2]), "+f"(c[3])
                 : "r"(a[0]), "r"(a[1]), "r"(a[2]), "r"(a[3]), "r"(b[0]), "r"(b[1]));
}

// ============================================================================
// Prologue 1: weights fp32 [o][c][9] -> fp16 [j][o][c]
// ============================================================================
__global__ void ta_conv_weights(const float* __restrict__ w) {
    int i = blockIdx.x * 256 + threadIdx.x;
    if (i >= 9 * 64 * 64) return;
    int j = i >> 12;
    int rem = i & 4095;
    int o = rem >> 6;
    int c = rem & 63;
    g_wh[j * 4096 + o * 64 + c] = __float2half_rn(w[(o * 64 + c) * 9 + j]);
}

// ============================================================================
// Prologue 2: x fp32 [b][c][t] -> fp16 [b][t][c], smem transpose (proven).
// ============================================================================
__global__ __launch_bounds__(256) void ta_prep(const float* __restrict__ x) {
    __shared__ float s1[128 * P1];        // 33.8 KB
    int tid = threadIdx.x;
    int wid = tid >> 5;
    int lane = tid & 31;
    int b = blockIdx.y;
    int t0 = blockIdx.x * 128;

    // Phase A: coalesced float4 reads along t, scalar transposed STS
    {
        int c = tid >> 2;
        int q0 = tid & 3;
        const float* xrow = x + ((size_t)(b * 64 + c)) * T_DIM + t0;
        #pragma unroll
        for (int q = q0; q < 32; q += 4) {
            float4 v = *(const float4*)(xrow + q * 4);
            int t = q * 4;
            s1[(t + 0) * P1 + c] = v.x;
            s1[(t + 1) * P1 + c] = v.y;
            s1[(t + 2) * P1 + c] = v.z;
            s1[(t + 3) * P1 + c] = v.w;
        }
    }
    __syncthreads();

    // Phase B: one warp per t-row, float2 LDS + coalesced STG
    {
        uint32_t* orow = (uint32_t*)g_xh;
        #pragma unroll
        for (int r = wid; r < 128; r += 8) {
            float2 f = *(const float2*)(s1 + r * P1 + 2 * lane);
            orow[((size_t)b * T_DIM + t0 + r) * 32 + lane] = pack_half2(f.x, f.y);
        }
    }
}

// ============================================================================
// Main kernel: block = [256 t][64 o]; 8 warps, each a 32x64 warp tile.
//   2 CTAs/SM. Taps factored as delta = d + 16*(g-1): per (kk,d) load 4
//   consecutive m16 A-fragments (rows tb+d-16 .. tb+d+32), reuse overlapping
//   pairs {f_g, f_{g+1}} for the 3 g-taps. Fully unrolled for ptxas scheduling.
// ============================================================================
__global__ __launch_bounds__(256, 2) void ta_main(const float* __restrict__ bias,
                                                  float* __restrict__ out) {
    extern __shared__ char smem[];
    uint32_t sb = smem_to_u32(smem);
    int tid = threadIdx.x;
    int wid = tid >> 5;
    int lane = tid & 31;

    int b = blockIdx.x >> 8;                    // 256 blocks per batch element
    int t0 = (blockIdx.x & 255) * TILE_M;

    if (tid < 64) ((float*)(smem + OFF_BIAS))[tid] = bias[tid];

    // ---- stage weights + x tile via cp.async, SW128-XOR swizzled ----
    {
        const char* wsrc = (const char*)g_wh;
        for (int i = tid; i < 576 * 8; i += 256) {
            int row = i >> 3, ch = i & 7;
            uint32_t dst = sb + OFF_W + row * 128 + ((ch ^ (row & 7)) * 16);
            cp_async16(dst, wsrc + row * 128 + ch * 16, 16);
        }
        for (int i = tid; i < XROWS * 8; i += 256) {
            int s = i >> 3, ch = i & 7;
            int t = t0 - 17 + s;
            const char* src = (const char*)(g_xh + ((size_t)b * T_DIM + t) * 64) + ch * 16;
            uint32_t dst = sb + OFF_X + s * 128 + ((ch ^ (s & 7)) * 16);
            cp_async16(dst, src, ((unsigned)t < (unsigned)T_DIM) ? 16 : 0);
        }
        CP_COMMIT();
    }

    // lane-dependent ldmatrix address components
    const int a_lrow = lane & 15;
    const int a_lcol = (lane >> 4) << 3;                 // 0 or 8 (halves)
    const int b_lrow = ((lane & 16) >> 1) + (lane & 7);  // 0..15
    const int b_lcol = lane & 8;                         // 0 or 8 (halves)
    const int b_sw = b_lrow & 7;

    const uint32_t wbase = sb + OFF_W;
    const uint32_t xbase = sb + OFF_X;

    float acc[2][8][4];
    #pragma unroll
    for (int mi = 0; mi < 2; mi++)
        #pragma unroll
        for (int ni = 0; ni < 8; ni++)
            #pragma unroll
            for (int r = 0; r < 4; r++) acc[mi][ni][r] = 0.0f;

    CP_WAIT0();
    __syncthreads();

    const int tb = 17 + wid * 32 + a_lrow;      // lane's base A row (tap delta 0)

    #pragma unroll
    for (int kk = 0; kk < 4; kk++) {
        const int c0 = kk * 16;
        const uint32_t bchunk = (uint32_t)((((c0 + b_lcol) >> 3) ^ b_sw) * 16);
        #pragma unroll
        for (int d = -1; d <= 1; d++) {
            const int rowbase = tb + d - 16;               // fragment f0 row
            const int a_sw = rowbase & 7;                  // same for all 4 frags
            const uint32_t achunk = (uint32_t)((((c0 + a_lcol) >> 3) ^ a_sw) * 16);
            uint32_t af[4][4];
            #pragma unroll
            for (int i = 0; i < 4; i++)
                ldsm4(af[i][0], af[i][1], af[i][2], af[i][3],
                      xbase + (uint32_t)(rowbase + i * 16) * 128 + achunk);
            #pragma unroll
            for (int g = 0; g < 3; g++) {
                const int j = 3 * g + (d + 1);             // tap index, delta=d+16(g-1)
                const uint32_t wj = wbase + j * WJ_BYTES;
                uint32_t bb[4][4];
                #pragma unroll
                for (int bi = 0; bi < 4; bi++)
                    ldsm4(bb[bi][0], bb[bi][1], bb[bi][2], bb[bi][3],
                          wj + (uint32_t)(bi * 16 + b_lrow) * 128 + bchunk);
                #pragma unroll
                for (int mi = 0; mi < 2; mi++)
                    #pragma unroll
                    for (int bi = 0; bi < 4; bi++) {
                        mma16816(acc[mi][2 * bi], af[g + mi], bb[bi] + 0);
                        mma16816(acc[mi][2 * bi + 1], af[g + mi], bb[bi] + 2);
                    }
            }
        }
    }

    // ---- epilogue: D fragment (row=t, col=o), add bias, store ----
    {
        const float* sbias = (const float*)(smem + OFF_BIAS);
        int trow = t0 + wid * 32 + (lane >> 2);
        int ocol = 2 * (lane & 3);
        #pragma unroll
        for (int mi = 0; mi < 2; mi++) {
            #pragma unroll
            for (int ni = 0; ni < 8; ni++) {
                int t = trow + mi * 16;
                int o = ocol + ni * 8;
                size_t base = ((size_t)b * 64 + o) * T_DIM + t;
                float bz0 = sbias[o], bz1 = sbias[o + 1];
                out[base] = acc[mi][ni][0] + bz0;
                out[base + T_DIM] = acc[mi][ni][1] + bz1;
                out[base + 8] = acc[mi][ni][2] + bz0;
                out[base + T_DIM + 8] = acc[mi][ni][3] + bz1;
            }
        }
    }
}

// ============================================================================
// Launch
// ============================================================================
extern "C" void kernel_launch(void* const* d_in, const int* in_sizes, int n_in,
                              void* d_out, int out_size) {
    const float* x = (const float*)d_in[0];
    const float* w = (const float*)d_in[1];
    const float* bias = (const float*)d_in[2];
    float* out = (float*)d_out;

    cudaFuncSetAttribute(ta_main, cudaFuncAttributeMaxDynamicSharedMemorySize, SMEM_TOTAL);

    ta_conv_weights<<<(9 * 64 * 64 + 255) / 256, 256>>>(w);
    ta_prep<<<dim3(T_DIM / 128, B_DIM), 256>>>(x);
    ta_main<<<(B_DIM * T_DIM) / TILE_M, 256, SMEM_TOTAL>>>(bias, out);
}